// round 15
// baseline (speedup 1.0000x reference)
#include <cuda_runtime.h>
#include <cuda_fp16.h>
#include <cstdint>
#include <math.h>

// Problem constants
#define DIMC     512
#define M_TOTAL  100352      // 8*256*49
#define SEQ      49
#define NWIN     2048        // 8*256
#define SCALEQ   0.17677669529663687f   // 32^-0.5
#define NMBLK    784         // GEMM M blocks (128 rows each)
#define GEMM_CTAS 6272       // 8 * 784

// Scratch (__device__ globals)
__device__ __half g_Ah [(size_t)M_TOTAL * DIMC];   // xh : GEMM A operand AND attn K-hi
__device__ __half g_Al [(size_t)M_TOTAL * DIMC];   // xl : attn K-lo
__device__ __half g_Yh [(size_t)M_TOTAL * DIMC];   // Y hi  (Q)
__device__ __half g_Vh [(size_t)M_TOTAL * DIMC];   // v (+bias) fp16
__device__ __half g_Bh [(size_t)1024 * DIMC];      // GEMM B rows
__device__ float  g_t2 [M_TOTAL];
__device__ float  g_w2 [DIMC];
__device__ int    g_ready[NMBLK];                  // per-M-block completion (0..8)

// ---------------------------------------------------------------------------
// Helpers
// ---------------------------------------------------------------------------
__device__ __forceinline__ uint32_t smem_u32(const void* p) {
    uint32_t a;
    asm("{ .reg .u64 t; cvta.to.shared.u64 t, %1; cvt.u32.u64 %0, t; }" : "=r"(a) : "l"(p));
    return a;
}
__device__ __forceinline__ void cp16(uint32_t s, const void* g) {
    asm volatile("cp.async.cg.shared.global [%0], [%1], 16;" :: "r"(s), "l"(g));
}
__device__ __forceinline__ void ldsm4(uint32_t* r, uint32_t addr) {
    asm volatile("ldmatrix.sync.aligned.m8n8.x4.shared.b16 {%0,%1,%2,%3}, [%4];"
        : "=r"(r[0]), "=r"(r[1]), "=r"(r[2]), "=r"(r[3]) : "r"(addr));
}
__device__ __forceinline__ void ldsm4t(uint32_t* r, uint32_t addr) {
    asm volatile("ldmatrix.sync.aligned.m8n8.x4.trans.shared.b16 {%0,%1,%2,%3}, [%4];"
        : "=r"(r[0]), "=r"(r[1]), "=r"(r[2]), "=r"(r[3]) : "r"(addr));
}
__device__ __forceinline__ void mma16816(float* d, const uint32_t* a, uint32_t b0, uint32_t b1) {
    asm volatile("mma.sync.aligned.m16n8k16.row.col.f32.f16.f16.f32 "
        "{%0,%1,%2,%3}, {%4,%5,%6,%7}, {%8,%9}, {%0,%1,%2,%3};"
        : "+f"(d[0]), "+f"(d[1]), "+f"(d[2]), "+f"(d[3])
        : "r"(a[0]), "r"(a[1]), "r"(a[2]), "r"(a[3]), "r"(b0), "r"(b1));
}

// ---------------------------------------------------------------------------
// prep_w2
// ---------------------------------------------------------------------------
__global__ __launch_bounds__(256)
void prep_w2_kernel(const float* __restrict__ W, const float* __restrict__ bias)
{
    int c = blockIdx.x * 256 + threadIdx.x;
    const float* row = W + (size_t)c * 1536 + 512;
    float s = 0.0f;
    for (int a = 0; a < DIMC; a++) s += row[a] * bias[a];
    g_w2[c] = SCALEQ * s;
}

// ---------------------------------------------------------------------------
// convert_x: x -> g_Ah (hi) + g_Al (lo); g_t2[m] = x_m . g_w2
// ---------------------------------------------------------------------------
__global__ __launch_bounds__(256)
void convert_x_kernel(const float* __restrict__ x)
{
    __shared__ float red[2][4];
    const int tid = threadIdx.x;
    size_t i4 = (size_t)blockIdx.x * 256 + tid;
    float4 v = reinterpret_cast<const float4*>(x)[i4];
    const int kq = (int)(i4 & 127);

    __half2 h0 = __floats2half2_rn(v.x, v.y);
    __half2 h1 = __floats2half2_rn(v.z, v.w);
    __half2 l0 = __floats2half2_rn(v.x - __low2float(h0), v.y - __high2float(h0));
    __half2 l1 = __floats2half2_rn(v.z - __low2float(h1), v.w - __high2float(h1));
    uint2 uh, ul;
    uh.x = *reinterpret_cast<uint32_t*>(&h0);
    uh.y = *reinterpret_cast<uint32_t*>(&h1);
    ul.x = *reinterpret_cast<uint32_t*>(&l0);
    ul.y = *reinterpret_cast<uint32_t*>(&l1);
    *reinterpret_cast<uint2*>(g_Ah + i4 * 4) = uh;
    *reinterpret_cast<uint2*>(g_Al + i4 * 4) = ul;

    float4 wv = *reinterpret_cast<const float4*>(&g_w2[kq * 4]);
    float p = v.x * wv.x + v.y * wv.y + v.z * wv.z + v.w * wv.w;
    #pragma unroll
    for (int o = 16; o > 0; o >>= 1) p += __shfl_down_sync(0xFFFFFFFFu, p, o);
    const int w = tid >> 5;
    if ((tid & 31) == 0) red[w >> 2][w & 3] = p;
    __syncthreads();
    if ((tid & 127) == 0) {
        const int r = tid >> 7;
        g_t2[blockIdx.x * 2 + r] = red[r][0] + red[r][1] + red[r][2] + red[r][3];
    }
}

// ---------------------------------------------------------------------------
// prep_M: M'[c1][c2] = SCALE * sum_a W[c1][a] * W[c2][512+a]
// ---------------------------------------------------------------------------
__global__ __launch_bounds__(256)
void prep_M_kernel(const float* __restrict__ W)
{
    __shared__ float sQ[16][68];
    __shared__ float sK[16][68];
    const int tid = threadIdx.x;
    const int tx = tid & 15, ty = tid >> 4;
    const int c1b = blockIdx.y * 64;
    const int c2b = blockIdx.x * 64;

    const int r  = tid >> 2;
    const int aq = (tid & 3) * 4;

    float acc[4][4];
    #pragma unroll
    for (int i = 0; i < 4; i++)
        #pragma unroll
        for (int j = 0; j < 4; j++) acc[i][j] = 0.0f;

    for (int a0 = 0; a0 < DIMC; a0 += 16) {
        __syncthreads();
        float4 wq = *reinterpret_cast<const float4*>(&W[(size_t)(c1b + r) * 1536 + a0 + aq]);
        float4 wk = *reinterpret_cast<const float4*>(&W[(size_t)(c2b + r) * 1536 + 512 + a0 + aq]);
        sQ[aq + 0][r] = wq.x; sQ[aq + 1][r] = wq.y; sQ[aq + 2][r] = wq.z; sQ[aq + 3][r] = wq.w;
        sK[aq + 0][r] = wk.x; sK[aq + 1][r] = wk.y; sK[aq + 2][r] = wk.z; sK[aq + 3][r] = wk.w;
        __syncthreads();

        #pragma unroll
        for (int a = 0; a < 16; a++) {
            float4 q = *reinterpret_cast<const float4*>(&sQ[a][ty * 4]);
            float4 k = *reinterpret_cast<const float4*>(&sK[a][tx * 4]);
            float qa[4] = {q.x, q.y, q.z, q.w};
            float ka[4] = {k.x, k.y, k.z, k.w};
            #pragma unroll
            for (int i = 0; i < 4; i++)
                #pragma unroll
                for (int j = 0; j < 4; j++)
                    acc[i][j] = fmaf(qa[i], ka[j], acc[i][j]);
        }
    }

    #pragma unroll
    for (int j = 0; j < 4; j++) {
        const int c2 = c2b + tx * 4 + j;
        #pragma unroll
        for (int i = 0; i < 4; i++) {
            const int c1 = c1b + ty * 4 + i;
            g_Bh[(size_t)c2 * DIMC + c1] = __float2half_rn(SCALEQ * acc[i][j]);
        }
    }
}

// prep_v
__global__ __launch_bounds__(256)
void prep_v_kernel(const float* __restrict__ W)
{
    int idx = blockIdx.x * 256 + threadIdx.x;
    int c  = idx >> 9;
    int nv = idx & 511;
    g_Bh[(size_t)(512 + nv) * DIMC + c] = __float2half_rn(W[(size_t)c * 1536 + 1024 + nv]);
}

// ---------------------------------------------------------------------------
// FUSED kernel: bid < GEMM_CTAS -> GEMM role; else attention role (waits on
// per-M-block counters). GEMM CTAs come first in bid order -> they are
// scheduled first and never wait -> forward progress guaranteed.
// ---------------------------------------------------------------------------
#define ROWB         80
#define TILE_BYTES_G (128 * ROWB)
#define STAGE_BYTES  (2 * TILE_BYTES_G)
#define FUSED_SMEM   (3 * STAGE_BYTES)       // 61440 (>= attn's 55552)
#define NCHUNK       (DIMC / 32)

// attn smem layout
#define CPITCH   144
#define PPITCH   72
#define REG      9216
#define QH0_OFF  0
#define KH0_OFF  18432
#define KL0_OFF  36864
#define SS_OFF   0
#define SP_OFF   18432
#define VB0_OFF  36864
#define VB1_OFF  46080
#define T2_OFF   55296

__global__ __launch_bounds__(256, 2)
void fused_kernel(const float* __restrict__ bias, float* __restrict__ out)
{
    extern __shared__ char smb[];
    const uint32_t sbase = smem_u32(smb);
    const int tid  = threadIdx.x;
    const int wid  = tid >> 5;
    const int lane = tid & 31;
    const uint32_t lrow = (uint32_t)(lane & 15);
    const uint32_t lcol = (uint32_t)((lane & 16) ? 16 : 0);

    if (blockIdx.x < GEMM_CTAS) {
        // ==================== GEMM role ====================
        const int bid  = blockIdx.x;
        const int bn0  = (bid & 7) * 128;
        const int bm   = bid >> 3;
        const int bm0  = bm * 128;
        const int wm   = wid >> 1;
        const int wn   = wid & 1;

        const int rc = tid >> 2;
        const int jc = tid & 3;
        const __half* Ag = g_Ah + (size_t)(bm0 + rc) * DIMC + jc * 8;
        const __half* Bg = g_Bh + (size_t)(bn0 + rc) * DIMC + jc * 8;
        const uint32_t sA_off = (uint32_t)(rc * ROWB + jc * 16);

        float acc[2][8][4];
        #pragma unroll
        for (int mi = 0; mi < 2; mi++)
            #pragma unroll
            for (int ni = 0; ni < 8; ni++)
                #pragma unroll
                for (int t = 0; t < 4; t++) acc[mi][ni][t] = 0.0f;

        #define ISSUE_STAGE(cc) do {                                             \
            const int _k0 = (cc) * 32;                                           \
            const uint32_t _st = sbase + ((cc) % 3) * STAGE_BYTES;               \
            cp16(_st + sA_off,                            Ag + _k0);             \
            cp16(_st + sA_off + 64 * ROWB,                Ag + (size_t)64 * DIMC + _k0); \
            cp16(_st + TILE_BYTES_G + sA_off,             Bg + _k0);             \
            cp16(_st + TILE_BYTES_G + sA_off + 64 * ROWB, Bg + (size_t)64 * DIMC + _k0); \
            asm volatile("cp.async.commit_group;" ::: "memory");                 \
        } while (0)

        ISSUE_STAGE(0);
        ISSUE_STAGE(1);

        for (int c = 0; c < NCHUNK; ++c) {
            if (c + 2 < NCHUNK) {
                asm volatile("cp.async.wait_group 1;" ::: "memory");
            } else {
                asm volatile("cp.async.wait_group 0;" ::: "memory");
            }
            __syncthreads();
            if (c + 2 < NCHUNK) ISSUE_STAGE(c + 2);

            const uint32_t sAu = sbase + (c % 3) * STAGE_BYTES;
            const uint32_t sBu = sAu + TILE_BYTES_G;
            const uint32_t aBase = sAu + (wm * 32 + lrow) * ROWB + lcol;
            const uint32_t bBase = sBu + (wn * 64 + lrow) * ROWB + lcol;

            #pragma unroll
            for (int ks = 0; ks < 2; ks++) {
                uint32_t afr[2][4];
                ldsm4(afr[0], aBase + ks * 32);
                ldsm4(afr[1], aBase + 16 * ROWB + ks * 32);
                #pragma unroll
                for (int pi = 0; pi < 4; pi++) {
                    uint32_t bfr[4];
                    ldsm4(bfr, bBase + pi * 16 * ROWB + ks * 32);
                    mma16816(acc[0][2 * pi + 0], afr[0], bfr[0], bfr[2]);
                    mma16816(acc[0][2 * pi + 1], afr[0], bfr[1], bfr[3]);
                    mma16816(acc[1][2 * pi + 0], afr[1], bfr[0], bfr[2]);
                    mma16816(acc[1][2 * pi + 1], afr[1], bfr[1], bfr[3]);
                }
            }
        }
        #undef ISSUE_STAGE

        // epilogue
        const bool isv = (bn0 >= DIMC);
        const int r0 = bm0 + (wid >> 1) * 32 + (lane >> 2);
        const int c0 = bn0 + (wid & 1) * 64 + (lane & 3) * 2;
        #pragma unroll
        for (int ni = 0; ni < 8; ni++) {
            const int col = c0 + ni * 8;
            float2 bb = make_float2(0.0f, 0.0f);
            if (isv) bb = *reinterpret_cast<const float2*>(&bias[512 + col]);
            #pragma unroll
            for (int mi = 0; mi < 2; mi++) {
                const int row = r0 + mi * 16;
                #pragma unroll
                for (int h = 0; h < 2; h++) {
                    const float vx = acc[mi][ni][2 * h + 0] + bb.x;
                    const float vy = acc[mi][ni][2 * h + 1] + bb.y;
                    const size_t o = (size_t)(row + 8 * h) * DIMC + (col - (isv ? DIMC : 0));
                    __half2 hh = __floats2half2_rn(vx, vy);
                    if (isv) *reinterpret_cast<__half2*>(&g_Vh[o]) = hh;
                    else     *reinterpret_cast<__half2*>(&g_Yh[o]) = hh;
                }
            }
        }

        // signal completion of this (bm, bn) tile
        __syncthreads();
        __threadfence();
        if (tid == 0) atomicAdd(&g_ready[bm], 1);
        return;
    }

    // ==================== Attention role ====================
    const int w = blockIdx.x - GEMM_CTAS;
    const size_t base = (size_t)w * SEQ;
    const int wm = wid >> 1;
    const int wn = wid & 1;

    // wait for the 1-2 GEMM M-blocks covering rows [base, base+48]
    if (tid == 0) {
        const int b0 = (int)(base >> 7);
        const int b1 = (int)((base + 48) >> 7);
        while (atomicAdd(&g_ready[b0], 0) < 8) __nanosleep(200);
        while (atomicAdd(&g_ready[b1], 0) < 8) __nanosleep(200);
    }
    __syncthreads();

    float* sT2 = reinterpret_cast<float*>(smb + T2_OFF);
    if (tid < SEQ) sT2[tid] = g_t2[base + tid];

    // zero pad rows 49..63 of all 6 regions
    for (int idx = tid; idx < 2880; idx += 256) {
        const int region = idx / 480;
        const int rem    = idx % 480;
        *reinterpret_cast<uint32_t*>(smb + region * REG +
            (49 + rem / 32) * CPITCH + (rem % 32) * 4) = 0;
    }

    #define STAGE64(gp, soff, cc) \
        for (int t = tid; t < 392; t += 256) { \
            const int row = t >> 3; const int ck = t & 7; \
            cp16(sbase + (soff) + row * CPITCH + ck * 16, \
                 (gp) + (size_t)(base + row) * DIMC + (cc) * 64 + ck * 8); \
        }
    #define STAGE_S(cc, b) do { \
        STAGE64(g_Yh, QH0_OFF + (b) * REG, cc) \
        STAGE64(g_Ah, KH0_OFF + (b) * REG, cc) \
        STAGE64(g_Al, KL0_OFF + (b) * REG, cc) \
        asm volatile("cp.async.commit_group;" ::: "memory"); \
    } while (0)

    float accS[4][4];
    #pragma unroll
    for (int nt = 0; nt < 4; nt++)
        #pragma unroll
        for (int t = 0; t < 4; t++) accS[nt][t] = 0.0f;

    STAGE_S(0, 0);
    STAGE_S(1, 1);

    for (int ch = 0; ch < 8; ch++) {
        if (ch < 7) asm volatile("cp.async.wait_group 1;" ::: "memory");
        else        asm volatile("cp.async.wait_group 0;" ::: "memory");
        __syncthreads();

        const int b = ch & 1;
        const uint32_t aQh = sbase + QH0_OFF + b * REG + (wm * 16 + lrow) * CPITCH + lcol;
        const uint32_t bKh = sbase + KH0_OFF + b * REG + (wn * 32 + lrow) * CPITCH + lcol;
        const uint32_t bKl = bKh + (KL0_OFF - KH0_OFF);

        #pragma unroll
        for (int ks = 0; ks < 4; ks++) {
            const uint32_t off = ks * 32;
            uint32_t qh[4];
            ldsm4(qh, aQh + off);
            #pragma unroll
            for (int g = 0; g < 2; g++) {
                uint32_t kh[4], kl[4];
                ldsm4(kh, bKh + g * 16 * CPITCH + off);
                ldsm4(kl, bKl + g * 16 * CPITCH + off);
                mma16816(accS[g * 2 + 0], qh, kh[0], kh[2]);
                mma16816(accS[g * 2 + 1], qh, kh[1], kh[3]);
                mma16816(accS[g * 2 + 0], qh, kl[0], kl[2]);
                mma16816(accS[g * 2 + 1], qh, kl[1], kl[3]);
            }
        }
        __syncthreads();
        if (ch + 2 < 8) STAGE_S(ch + 2, ch & 1);
    }

    STAGE64(g_Vh, VB0_OFF, 0)
    asm volatile("cp.async.commit_group;" ::: "memory");

    float* sS = reinterpret_cast<float*>(smb + SS_OFF);
    {
        const int fr = lane >> 2;
        const int fc = (lane & 3) * 2;
        #pragma unroll
        for (int nt = 0; nt < 4; nt++) {
            const int col = wn * 32 + nt * 8 + fc;
            *reinterpret_cast<float2*>(&sS[(wm * 16 + fr) * 68 + col]) =
                make_float2(accS[nt][0], accS[nt][1]);
            *reinterpret_cast<float2*>(&sS[(wm * 16 + fr + 8) * 68 + col]) =
                make_float2(accS[nt][2], accS[nt][3]);
        }
    }
    __syncthreads();

    __half* sP = reinterpret_cast<__half*>(smb + SP_OFF);
    for (int r = wid; r < 64; r += 8) {
        const float* row = sS + r * 68;
        const float v0 = (lane < SEQ)      ? row[lane]      + sT2[lane]      : -1e30f;
        const float v1 = (lane + 32 < SEQ) ? row[lane + 32] + sT2[lane + 32] : -1e30f;
        float mx = fmaxf(v0, v1);
        #pragma unroll
        for (int o = 16; o > 0; o >>= 1)
            mx = fmaxf(mx, __shfl_xor_sync(0xFFFFFFFFu, mx, o));
        const float e0 = (lane < SEQ)      ? __expf(v0 - mx) : 0.0f;
        const float e1 = (lane + 32 < SEQ) ? __expf(v1 - mx) : 0.0f;
        float s = e0 + e1;
        #pragma unroll
        for (int o = 16; o > 0; o >>= 1)
            s += __shfl_xor_sync(0xFFFFFFFFu, s, o);
        const float inv = 1.0f / s;
        sP[r * PPITCH + lane]      = __float2half_rn(e0 * inv);
        sP[r * PPITCH + lane + 32] = __float2half_rn(e1 * inv);
    }
    __syncthreads();

    STAGE64(g_Vh, VB1_OFF, 1)
    asm volatile("cp.async.commit_group;" ::: "memory");

    const int fr = lane >> 2;
    const int fc = (lane & 3) * 2;
    const int r0 = wm * 16 + fr;
    const uint32_t aP0 = sbase + SP_OFF + (wm * 16 + lrow) * (PPITCH * 2) + lcol;

    for (int ch = 0; ch < 8; ch++) {
        if (ch < 7) asm volatile("cp.async.wait_group 1;" ::: "memory");
        else        asm volatile("cp.async.wait_group 0;" ::: "memory");
        __syncthreads();

        const uint32_t vbuf = sbase + ((ch & 1) ? VB1_OFF : VB0_OFF);

        float accv[4][4];
        #pragma unroll
        for (int nt = 0; nt < 4; nt++)
            #pragma unroll
            for (int t = 0; t < 4; t++) accv[nt][t] = 0.0f;

        #pragma unroll
        for (int ks = 0; ks < 4; ks++) {
            uint32_t pf[4];
            ldsm4(pf, aP0 + ks * 32);
            #pragma unroll
            for (int g = 0; g < 2; g++) {
                const uint32_t vaddr = vbuf + (ks * 16 + lrow) * CPITCH
                                     + (uint32_t)((wn * 32 + g * 16 + 8 * (lane >> 4)) * 2);
                uint32_t vh[4];
                ldsm4t(vh, vaddr);
                mma16816(accv[g * 2 + 0], pf, vh[0], vh[1]);
                mma16816(accv[g * 2 + 1], pf, vh[2], vh[3]);
            }
        }

        #pragma unroll
        for (int nt = 0; nt < 4; nt++) {
            const int col = ch * 64 + wn * 32 + (nt >> 1) * 16 + (nt & 1) * 8 + fc;
            if (r0 < SEQ)
                *reinterpret_cast<float2*>(&out[(base + r0) * DIMC + col]) =
                    make_float2(accv[nt][0], accv[nt][1]);
            if (r0 + 8 < SEQ)
                *reinterpret_cast<float2*>(&out[(base + r0 + 8) * DIMC + col]) =
                    make_float2(accv[nt][2], accv[nt][3]);
        }
        __syncthreads();
        if (ch + 2 < 8) {
            const uint32_t voff = (ch & 1) ? VB1_OFF : VB0_OFF;
            STAGE64(g_Vh, voff, ch + 2)
            asm volatile("cp.async.commit_group;" ::: "memory");
        }
    }
    #undef STAGE64
    #undef STAGE_S
}

// ---------------------------------------------------------------------------
extern "C" void kernel_launch(void* const* d_in, const int* in_sizes, int n_in,
                              void* d_out, int out_size)
{
    const float* x    = (const float*)d_in[0];
    // d_in[1] = x_all : unused by the reference
    const float* W    = (const float*)d_in[2];
    const float* bias = (const float*)d_in[3];
    float* out        = (float*)d_out;

    cudaFuncSetAttribute(fused_kernel,
                         cudaFuncAttributeMaxDynamicSharedMemorySize, FUSED_SMEM);

    // reset readiness counters (graph-capturable, no allocation)
    void* raddr = nullptr;
    cudaGetSymbolAddress(&raddr, g_ready);
    cudaMemsetAsync(raddr, 0, sizeof(int) * NMBLK);

    prep_w2_kernel<<<2, 256>>>(W, bias);
    convert_x_kernel<<<(M_TOTAL * (DIMC / 4)) / 256, 256>>>(x);   // 50176 blocks
    prep_M_kernel<<<dim3(8, 8), 256>>>(W);
    prep_v_kernel<<<(DIMC * DIMC) / 256, 256>>>(W);               // 1024 blocks

    fused_kernel<<<GEMM_CTAS + NWIN, 256, FUSED_SMEM>>>(bias, out);
}

// round 17
// speedup vs baseline: 1.0390x; 1.0390x over previous
#include <cuda_runtime.h>
#include <cuda_fp16.h>
#include <cstdint>
#include <math.h>

// Problem constants
#define DIMC     512
#define M_TOTAL  100352      // 8*256*49
#define SEQ      49
#define NWIN     2048        // 8*256
#define SCALEQ   0.17677669529663687f   // 32^-0.5

// Scratch (__device__ globals)
__device__ __half g_Ah [(size_t)M_TOTAL * DIMC];   // xh : GEMM A operand AND attn K-hi
__device__ __half g_Al [(size_t)M_TOTAL * DIMC];   // xl : attn K-lo
__device__ __half g_Yh [(size_t)M_TOTAL * DIMC];   // Y hi  (Q)
__device__ __half g_Vh [(size_t)M_TOTAL * DIMC];   // v (+bias) fp16
__device__ __half g_Bh [(size_t)1024 * DIMC];      // GEMM B rows: n<512 -> M'[:,n], else Wv
__device__ float  g_t2 [M_TOTAL];
__device__ float  g_w2 [DIMC];

// ---------------------------------------------------------------------------
// Helpers
// ---------------------------------------------------------------------------
__device__ __forceinline__ uint32_t smem_u32(const void* p) {
    uint32_t a;
    asm("{ .reg .u64 t; cvta.to.shared.u64 t, %1; cvt.u32.u64 %0, t; }" : "=r"(a) : "l"(p));
    return a;
}
__device__ __forceinline__ void cp16(uint32_t s, const void* g) {
    asm volatile("cp.async.cg.shared.global [%0], [%1], 16;" :: "r"(s), "l"(g));
}
__device__ __forceinline__ void ldsm4(uint32_t* r, uint32_t addr) {
    asm volatile("ldmatrix.sync.aligned.m8n8.x4.shared.b16 {%0,%1,%2,%3}, [%4];"
        : "=r"(r[0]), "=r"(r[1]), "=r"(r[2]), "=r"(r[3]) : "r"(addr));
}
__device__ __forceinline__ void ldsm4t(uint32_t* r, uint32_t addr) {
    asm volatile("ldmatrix.sync.aligned.m8n8.x4.trans.shared.b16 {%0,%1,%2,%3}, [%4];"
        : "=r"(r[0]), "=r"(r[1]), "=r"(r[2]), "=r"(r[3]) : "r"(addr));
}
__device__ __forceinline__ void mma16816(float* d, const uint32_t* a, uint32_t b0, uint32_t b1) {
    asm volatile("mma.sync.aligned.m16n8k16.row.col.f32.f16.f16.f32 "
        "{%0,%1,%2,%3}, {%4,%5,%6,%7}, {%8,%9}, {%0,%1,%2,%3};"
        : "+f"(d[0]), "+f"(d[1]), "+f"(d[2]), "+f"(d[3])
        : "r"(a[0]), "r"(a[1]), "r"(a[2]), "r"(a[3]), "r"(b0), "r"(b1));
}

// ---------------------------------------------------------------------------
// prep_w2: g_w2[c] = SCALE * sum_a W[c][512+a] * bias[a]
// ---------------------------------------------------------------------------
__global__ __launch_bounds__(256)
void prep_w2_kernel(const float* __restrict__ W, const float* __restrict__ bias)
{
    int c = blockIdx.x * 256 + threadIdx.x;
    const float* row = W + (size_t)c * 1536 + 512;
    float s = 0.0f;
    for (int a = 0; a < DIMC; a++) s += row[a] * bias[a];
    g_w2[c] = SCALEQ * s;
}

// ---------------------------------------------------------------------------
// convert_x: x -> g_Ah (hi) + g_Al (lo); g_t2[m] = x_m . g_w2
// ---------------------------------------------------------------------------
__global__ __launch_bounds__(256)
void convert_x_kernel(const float* __restrict__ x)
{
    __shared__ float red[2][4];
    const int tid = threadIdx.x;
    size_t i4 = (size_t)blockIdx.x * 256 + tid;
    float4 v = reinterpret_cast<const float4*>(x)[i4];
    const int kq = (int)(i4 & 127);

    __half2 h0 = __floats2half2_rn(v.x, v.y);
    __half2 h1 = __floats2half2_rn(v.z, v.w);
    __half2 l0 = __floats2half2_rn(v.x - __low2float(h0), v.y - __high2float(h0));
    __half2 l1 = __floats2half2_rn(v.z - __low2float(h1), v.w - __high2float(h1));
    uint2 uh, ul;
    uh.x = *reinterpret_cast<uint32_t*>(&h0);
    uh.y = *reinterpret_cast<uint32_t*>(&h1);
    ul.x = *reinterpret_cast<uint32_t*>(&l0);
    ul.y = *reinterpret_cast<uint32_t*>(&l1);
    *reinterpret_cast<uint2*>(g_Ah + i4 * 4) = uh;
    *reinterpret_cast<uint2*>(g_Al + i4 * 4) = ul;

    float4 wv = *reinterpret_cast<const float4*>(&g_w2[kq * 4]);
    float p = v.x * wv.x + v.y * wv.y + v.z * wv.z + v.w * wv.w;
    #pragma unroll
    for (int o = 16; o > 0; o >>= 1) p += __shfl_down_sync(0xFFFFFFFFu, p, o);
    const int w = tid >> 5;
    if ((tid & 31) == 0) red[w >> 2][w & 3] = p;
    __syncthreads();
    if ((tid & 127) == 0) {
        const int r = tid >> 7;
        g_t2[blockIdx.x * 2 + r] = red[r][0] + red[r][1] + red[r][2] + red[r][3];
    }
}

// ---------------------------------------------------------------------------
// prep_M: M'[c1][c2] = SCALE * sum_a W[c1][a] * W[c2][512+a]
// ---------------------------------------------------------------------------
__global__ __launch_bounds__(256)
void prep_M_kernel(const float* __restrict__ W)
{
    __shared__ float sQ[16][68];
    __shared__ float sK[16][68];
    const int tid = threadIdx.x;
    const int tx = tid & 15, ty = tid >> 4;
    const int c1b = blockIdx.y * 64;
    const int c2b = blockIdx.x * 64;

    const int r  = tid >> 2;
    const int aq = (tid & 3) * 4;

    float acc[4][4];
    #pragma unroll
    for (int i = 0; i < 4; i++)
        #pragma unroll
        for (int j = 0; j < 4; j++) acc[i][j] = 0.0f;

    for (int a0 = 0; a0 < DIMC; a0 += 16) {
        __syncthreads();
        float4 wq = *reinterpret_cast<const float4*>(&W[(size_t)(c1b + r) * 1536 + a0 + aq]);
        float4 wk = *reinterpret_cast<const float4*>(&W[(size_t)(c2b + r) * 1536 + 512 + a0 + aq]);
        sQ[aq + 0][r] = wq.x; sQ[aq + 1][r] = wq.y; sQ[aq + 2][r] = wq.z; sQ[aq + 3][r] = wq.w;
        sK[aq + 0][r] = wk.x; sK[aq + 1][r] = wk.y; sK[aq + 2][r] = wk.z; sK[aq + 3][r] = wk.w;
        __syncthreads();

        #pragma unroll
        for (int a = 0; a < 16; a++) {
            float4 q = *reinterpret_cast<const float4*>(&sQ[a][ty * 4]);
            float4 k = *reinterpret_cast<const float4*>(&sK[a][tx * 4]);
            float qa[4] = {q.x, q.y, q.z, q.w};
            float ka[4] = {k.x, k.y, k.z, k.w};
            #pragma unroll
            for (int i = 0; i < 4; i++)
                #pragma unroll
                for (int j = 0; j < 4; j++)
                    acc[i][j] = fmaf(qa[i], ka[j], acc[i][j]);
        }
    }

    #pragma unroll
    for (int j = 0; j < 4; j++) {
        const int c2 = c2b + tx * 4 + j;
        #pragma unroll
        for (int i = 0; i < 4; i++) {
            const int c1 = c1b + ty * 4 + i;
            g_Bh[(size_t)c2 * DIMC + c1] = __float2half_rn(SCALEQ * acc[i][j]);
        }
    }
}

// prep_v: g_Bh[(512+nv)*512 + c] = fp16(W[c][1024+nv])
__global__ __launch_bounds__(256)
void prep_v_kernel(const float* __restrict__ W)
{
    int idx = blockIdx.x * 256 + threadIdx.x;
    int c  = idx >> 9;
    int nv = idx & 511;
    g_Bh[(size_t)(512 + nv) * DIMC + c] = __float2half_rn(W[(size_t)c * 1536 + 1024 + nv]);
}

// ---------------------------------------------------------------------------
// HMMA GEMM: [Y | v] = Ah[M,512] x Bh[N,512]^T; epilogue -> fp16 stores
// ---------------------------------------------------------------------------
#define ROWB         80
#define TILE_BYTES_G (128 * ROWB)
#define STAGE_BYTES  (2 * TILE_BYTES_G)
#define GEMM_SMEM    (3 * STAGE_BYTES)
#define NCHUNK       (DIMC / 32)

__global__ __launch_bounds__(256, 2)
void z_gemm_mma(const float* __restrict__ bias)
{
    extern __shared__ char sbuf[];
    const uint32_t sbase = smem_u32(sbuf);

    const int tid  = threadIdx.x;
    const int wid  = tid >> 5;
    const int lane = tid & 31;
    const int wm   = wid >> 1;
    const int wn   = wid & 1;
    const int bn0  = blockIdx.x * 128;
    const int bm0  = blockIdx.y * 128;

    const int rc = tid >> 2;
    const int jc = tid & 3;
    const __half* Ag = g_Ah + (size_t)(bm0 + rc) * DIMC + jc * 8;
    const __half* Bg = g_Bh + (size_t)(bn0 + rc) * DIMC + jc * 8;
    const uint32_t sA_off = (uint32_t)(rc * ROWB + jc * 16);

    float acc[2][8][4];
    #pragma unroll
    for (int mi = 0; mi < 2; mi++)
        #pragma unroll
        for (int ni = 0; ni < 8; ni++)
            #pragma unroll
            for (int t = 0; t < 4; t++) acc[mi][ni][t] = 0.0f;

    const uint32_t lrow = (uint32_t)(lane & 15);
    const uint32_t lcol = (uint32_t)((lane & 16) ? 16 : 0);

    #define ISSUE_STAGE(cc) do {                                             \
        const int _k0 = (cc) * 32;                                           \
        const uint32_t _st = sbase + ((cc) % 3) * STAGE_BYTES;               \
        cp16(_st + sA_off,                            Ag + _k0);             \
        cp16(_st + sA_off + 64 * ROWB,                Ag + (size_t)64 * DIMC + _k0); \
        cp16(_st + TILE_BYTES_G + sA_off,             Bg + _k0);             \
        cp16(_st + TILE_BYTES_G + sA_off + 64 * ROWB, Bg + (size_t)64 * DIMC + _k0); \
        asm volatile("cp.async.commit_group;" ::: "memory");                 \
    } while (0)

    ISSUE_STAGE(0);
    ISSUE_STAGE(1);

    for (int c = 0; c < NCHUNK; ++c) {
        if (c + 2 < NCHUNK) {
            asm volatile("cp.async.wait_group 1;" ::: "memory");
        } else {
            asm volatile("cp.async.wait_group 0;" ::: "memory");
        }
        __syncthreads();
        if (c + 2 < NCHUNK) ISSUE_STAGE(c + 2);

        const uint32_t sAu = sbase + (c % 3) * STAGE_BYTES;
        const uint32_t sBu = sAu + TILE_BYTES_G;
        const uint32_t aBase = sAu + (wm * 32 + lrow) * ROWB + lcol;
        const uint32_t bBase = sBu + (wn * 64 + lrow) * ROWB + lcol;

        #pragma unroll
        for (int ks = 0; ks < 2; ks++) {
            uint32_t afr[2][4];
            ldsm4(afr[0], aBase + ks * 32);
            ldsm4(afr[1], aBase + 16 * ROWB + ks * 32);
            #pragma unroll
            for (int pi = 0; pi < 4; pi++) {
                uint32_t bfr[4];
                ldsm4(bfr, bBase + pi * 16 * ROWB + ks * 32);
                mma16816(acc[0][2 * pi + 0], afr[0], bfr[0], bfr[2]);
                mma16816(acc[0][2 * pi + 1], afr[0], bfr[1], bfr[3]);
                mma16816(acc[1][2 * pi + 0], afr[1], bfr[0], bfr[2]);
                mma16816(acc[1][2 * pi + 1], afr[1], bfr[1], bfr[3]);
            }
        }
    }
    #undef ISSUE_STAGE

    // ---- epilogue
    const bool isv = (bn0 >= DIMC);
    const int r0 = bm0 + wm * 32 + (lane >> 2);
    const int c0 = bn0 + wn * 64 + (lane & 3) * 2;
    #pragma unroll
    for (int ni = 0; ni < 8; ni++) {
        const int col = c0 + ni * 8;
        float2 bb = make_float2(0.0f, 0.0f);
        if (isv) bb = *reinterpret_cast<const float2*>(&bias[512 + col]);
        #pragma unroll
        for (int mi = 0; mi < 2; mi++) {
            const int row = r0 + mi * 16;
            #pragma unroll
            for (int h = 0; h < 2; h++) {
                const float vx = acc[mi][ni][2 * h + 0] + bb.x;
                const float vy = acc[mi][ni][2 * h + 1] + bb.y;
                const size_t o = (size_t)(row + 8 * h) * DIMC + (col - (isv ? DIMC : 0));
                __half2 hh = __floats2half2_rn(vx, vy);
                if (isv) *reinterpret_cast<__half2*>(&g_Vh[o]) = hh;
                else     *reinterpret_cast<__half2*>(&g_Yh[o]) = hh;
            }
        }
    }
}

// ---------------------------------------------------------------------------
// HMMA attention, fully double-buffered, occupancy 4 (smem 55552*4 = 222KB).
// 8 chunks of 64 channels; region = 64 rows x 144 B.
//  S = Qh*(Kh + Kl); softmax(+t2) -> P fp16; O = P*Vh
// smem: QH0@0 QH1@9216 KH0@18432 KH1@27648 KL0@36864 KL1@46080
//       after S: sS fp32 @0, sP @18432; V double-buffer @36864/@46080
//       sT2 @55296 -> total 55552
// ---------------------------------------------------------------------------
#define CPITCH   144
#define PPITCH   72
#define REG      9216
#define QH0_OFF  0
#define KH0_OFF  18432
#define KL0_OFF  36864
#define SS_OFF   0
#define SP_OFF   18432
#define VB0_OFF  36864
#define VB1_OFF  46080
#define T2_OFF   55296
#define ATTN_SMEM_BYTES 55552

__global__ __launch_bounds__(256, 4)
void attn_kernel(float* __restrict__ out)
{
    extern __shared__ char smb[];
    const uint32_t sbase = smem_u32(smb);

    const int w    = blockIdx.x;
    const int tid  = threadIdx.x;
    const int wid  = tid >> 5;
    const int lane = tid & 31;
    const int wm   = wid >> 1;          // row tile (16 rows)
    const int wn   = wid & 1;           // col half (32 cols)
    const size_t base = (size_t)w * SEQ;

    float* sT2 = reinterpret_cast<float*>(smb + T2_OFF);
    if (tid < SEQ) sT2[tid] = g_t2[base + tid];

    // zero pad rows 49..63 of all 6 regions (V reuses KL -> pads stay zero)
    for (int idx = tid; idx < 2880; idx += 256) {
        const int region = idx / 480;
        const int rem    = idx % 480;
        *reinterpret_cast<uint32_t*>(smb + region * REG +
            (49 + rem / 32) * CPITCH + (rem % 32) * 4) = 0;
    }

    const uint32_t lrow = (uint32_t)(lane & 15);
    const uint32_t lcol = (uint32_t)((lane & 16) ? 16 : 0);

    // one 64-channel tile: 49 rows x 128 B
    #define STAGE64(gp, soff, cc) \
        for (int t = tid; t < 392; t += 256) { \
            const int row = t >> 3; const int ck = t & 7; \
            cp16(sbase + (soff) + row * CPITCH + ck * 16, \
                 (gp) + (size_t)(base + row) * DIMC + (cc) * 64 + ck * 8); \
        }
    #define STAGE_S(cc, b) do { \
        STAGE64(g_Yh, QH0_OFF + (b) * REG, cc) \
        STAGE64(g_Ah, KH0_OFF + (b) * REG, cc) \
        STAGE64(g_Al, KL0_OFF + (b) * REG, cc) \
        asm volatile("cp.async.commit_group;" ::: "memory"); \
    } while (0)

    float accS[4][4];
    #pragma unroll
    for (int nt = 0; nt < 4; nt++)
        #pragma unroll
        for (int t = 0; t < 4; t++) accS[nt][t] = 0.0f;

    STAGE_S(0, 0);
    STAGE_S(1, 1);

    // ================= Phase S: 8 chunks, 2-deep pipeline =================
    for (int ch = 0; ch < 8; ch++) {
        if (ch < 7) asm volatile("cp.async.wait_group 1;" ::: "memory");
        else        asm volatile("cp.async.wait_group 0;" ::: "memory");
        __syncthreads();

        const int b = ch & 1;
        const uint32_t aQh = sbase + QH0_OFF + b * REG + (wm * 16 + lrow) * CPITCH + lcol;
        const uint32_t bKh = sbase + KH0_OFF + b * REG + (wn * 32 + lrow) * CPITCH + lcol;
        const uint32_t bKl = bKh + (KL0_OFF - KH0_OFF);

        #pragma unroll
        for (int ks = 0; ks < 4; ks++) {
            const uint32_t off = ks * 32;
            uint32_t qh[4];
            ldsm4(qh, aQh + off);
            #pragma unroll
            for (int g = 0; g < 2; g++) {
                uint32_t kh[4], kl[4];
                ldsm4(kh, bKh + g * 16 * CPITCH + off);
                ldsm4(kl, bKl + g * 16 * CPITCH + off);
                mma16816(accS[g * 2 + 0], qh, kh[0], kh[2]);
                mma16816(accS[g * 2 + 1], qh, kh[1], kh[3]);
                mma16816(accS[g * 2 + 0], qh, kl[0], kl[2]);
                mma16816(accS[g * 2 + 1], qh, kl[1], kl[3]);
            }
        }
        __syncthreads();
        if (ch + 2 < 8) STAGE_S(ch + 2, ch & 1);
    }

    // ---- prefetch V chunk 0 (KL0 region dead), store S, softmax ----
    STAGE64(g_Vh, VB0_OFF, 0)
    asm volatile("cp.async.commit_group;" ::: "memory");

    float* sS = reinterpret_cast<float*>(smb + SS_OFF);
    {
        const int fr = lane >> 2;
        const int fc = (lane & 3) * 2;
        #pragma unroll
        for (int nt = 0; nt < 4; nt++) {
            const int col = wn * 32 + nt * 8 + fc;
            *reinterpret_cast<float2*>(&sS[(wm * 16 + fr) * 68 + col]) =
                make_float2(accS[nt][0], accS[nt][1]);
            *reinterpret_cast<float2*>(&sS[(wm * 16 + fr + 8) * 68 + col]) =
                make_float2(accS[nt][2], accS[nt][3]);
        }
    }
    __syncthreads();

    __half* sP = reinterpret_cast<__half*>(smb + SP_OFF);
    for (int r = wid; r < 64; r += 8) {
        const float* row = sS + r * 68;
        const float v0 = (lane < SEQ)      ? row[lane]      + sT2[lane]      : -1e30f;
        const float v1 = (lane + 32 < SEQ) ? row[lane + 32] + sT2[lane + 32] : -1e30f;
        float mx = fmaxf(v0, v1);
        #pragma unroll
        for (int o = 16; o > 0; o >>= 1)
            mx = fmaxf(mx, __shfl_xor_sync(0xFFFFFFFFu, mx, o));
        const float e0 = (lane < SEQ)      ? __expf(v0 - mx) : 0.0f;
        const float e1 = (lane + 32 < SEQ) ? __expf(v1 - mx) : 0.0f;
        float s = e0 + e1;
        #pragma unroll
        for (int o = 16; o > 0; o >>= 1)
            s += __shfl_xor_sync(0xFFFFFFFFu, s, o);
        const float inv = 1.0f / s;
        sP[r * PPITCH + lane]      = __float2half_rn(e0 * inv);
        sP[r * PPITCH + lane + 32] = __float2half_rn(e1 * inv);
    }
    __syncthreads();

    STAGE64(g_Vh, VB1_OFF, 1)
    asm volatile("cp.async.commit_group;" ::: "memory");

    // ================= Phase PV: 8 chunks, 2-deep pipeline =================
    const int fr = lane >> 2;
    const int fc = (lane & 3) * 2;
    const int r0 = wm * 16 + fr;
    const uint32_t aP0 = sbase + SP_OFF + (wm * 16 + lrow) * (PPITCH * 2) + lcol;

    for (int ch = 0; ch < 8; ch++) {
        if (ch < 7) asm volatile("cp.async.wait_group 1;" ::: "memory");
        else        asm volatile("cp.async.wait_group 0;" ::: "memory");
        __syncthreads();

        const uint32_t vbuf = sbase + ((ch & 1) ? VB1_OFF : VB0_OFF);

        float accv[4][4];
        #pragma unroll
        for (int nt = 0; nt < 4; nt++)
            #pragma unroll
            for (int t = 0; t < 4; t++) accv[nt][t] = 0.0f;

        #pragma unroll
        for (int ks = 0; ks < 4; ks++) {
            uint32_t pf[4];
            ldsm4(pf, aP0 + ks * 32);
            #pragma unroll
            for (int g = 0; g < 2; g++) {
                const uint32_t vaddr = vbuf + (ks * 16 + lrow) * CPITCH
                                     + (uint32_t)((wn * 32 + g * 16 + 8 * (lane >> 4)) * 2);
                uint32_t vh[4];
                ldsm4t(vh, vaddr);
                mma16816(accv[g * 2 + 0], pf, vh[0], vh[1]);
                mma16816(accv[g * 2 + 1], pf, vh[2], vh[3]);
            }
        }

        #pragma unroll
        for (int nt = 0; nt < 4; nt++) {
            const int col = ch * 64 + wn * 32 + (nt >> 1) * 16 + (nt & 1) * 8 + fc;
            if (r0 < SEQ)
                *reinterpret_cast<float2*>(&out[(base + r0) * DIMC + col]) =
                    make_float2(accv[nt][0], accv[nt][1]);
            if (r0 + 8 < SEQ)
                *reinterpret_cast<float2*>(&out[(base + r0 + 8) * DIMC + col]) =
                    make_float2(accv[nt][2], accv[nt][3]);
        }
        __syncthreads();
        if (ch + 2 < 8) {
            const uint32_t voff = (ch & 1) ? VB1_OFF : VB0_OFF;
            STAGE64(g_Vh, voff, ch + 2)
            asm volatile("cp.async.commit_group;" ::: "memory");
        }
    }
    #undef STAGE64
    #undef STAGE_S
}

// ---------------------------------------------------------------------------
extern "C" void kernel_launch(void* const* d_in, const int* in_sizes, int n_in,
                              void* d_out, int out_size)
{
    const float* x    = (const float*)d_in[0];
    // d_in[1] = x_all : unused by the reference
    const float* W    = (const float*)d_in[2];
    const float* bias = (const float*)d_in[3];
    float* out        = (float*)d_out;

    cudaFuncSetAttribute(z_gemm_mma,
                         cudaFuncAttributeMaxDynamicSharedMemorySize, GEMM_SMEM);
    cudaFuncSetAttribute(attn_kernel,
                         cudaFuncAttributeMaxDynamicSharedMemorySize, ATTN_SMEM_BYTES);
    cudaFuncSetAttribute(attn_kernel,
                         cudaFuncAttributePreferredSharedMemoryCarveout, 100);

    prep_w2_kernel<<<2, 256>>>(W, bias);
    convert_x_kernel<<<(M_TOTAL * (DIMC / 4)) / 256, 256>>>(x);   // 50176 blocks
    prep_M_kernel<<<dim3(8, 8), 256>>>(W);
    prep_v_kernel<<<(DIMC * DIMC) / 256, 256>>>(W);               // 1024 blocks

    dim3 gemm_grid(1024 / 128, M_TOTAL / 128);                    // 8 x 784
    z_gemm_mma<<<gemm_grid, 256, GEMM_SMEM>>>(bias);

    attn_kernel<<<NWIN, 256, ATTN_SMEM_BYTES>>>(out);
}